// round 1
// baseline (speedup 1.0000x reference)
#include <cuda_runtime.h>
#include <math.h>

#define BATCH    32768
#define DIM      256
#define MBLK     (BATCH/128)   // 256
#define NBLK     (DIM/128)     // 2
#define NCTAS    (MBLK*NBLK)   // 512
#define EW_GRID  (BATCH*DIM/4/256)  // 8192 blocks of 256 threads, float4 each
#define MAX_IT   40

// ---------------- device scratch (allowed: __device__ globals) ----------------
__device__ float g_x[BATCH*DIM];
__device__ float g_y[BATCH*DIM];
__device__ float g_G[BATCH*DIM];
__device__ float g_b[BATCH*DIM];
__device__ float g_W [DIM*DIM];   // Weff:  multiply(z) = z @ Weff
__device__ float g_WU[DIM*DIM];   // U^T:   bias = x @ g_WU + ub
__device__ float g_partial[NCTAS*2];
__device__ int   g_active;

// ---------------- packed fp32x2 helpers (sm_100+) ----------------
__device__ __forceinline__ unsigned long long pack2(float v) {
    unsigned long long r; unsigned u = __float_as_uint(v);
    asm("mov.b64 %0, {%1, %1};" : "=l"(r) : "r"(u));
    return r;
}
__device__ __forceinline__ void ffma2(unsigned long long& d,
                                      unsigned long long a,
                                      unsigned long long b) {
    asm("fma.rn.f32x2 %0, %1, %2, %0;" : "+l"(d) : "l"(a), "l"(b));
}
__device__ __forceinline__ float lo32(unsigned long long v) {
    return __uint_as_float((unsigned)(v & 0xffffffffull));
}
__device__ __forceinline__ float hi32(unsigned long long v) {
    return __uint_as_float((unsigned)(v >> 32));
}

// ---------------- prep: Weff and U^T ----------------
__global__ void prep_kernel(const float* __restrict__ U,
                            const float* __restrict__ A,
                            const float* __restrict__ B) {
    int i = blockIdx.x;    // 0..255
    int j = threadIdx.x;   // 0..255
    g_WU[i*DIM + j] = U[j*DIM + i];
    float s = 0.f;
#pragma unroll 8
    for (int p = 0; p < DIM; ++p)
        s = fmaf(A[p*DIM + i], A[p*DIM + j], s);
    float w = -s + B[j*DIM + i] - B[i*DIM + j];
    if (i == j) w += 0.8f;           // (1 - m), m = 0.2
    g_W[i*DIM + j] = w;
}

// ---------------- init: zero state, arm the flag ----------------
__global__ void init_kernel() {
    int i = blockIdx.x * blockDim.x + threadIdx.x;
    float4 z = make_float4(0.f, 0.f, 0.f, 0.f);
    ((float4*)g_x)[i] = z;
    ((float4*)g_y)[i] = z;
    ((float4*)g_G)[i] = z;
    if (i == 0) g_active = 1;
}

// ---------------- GEMM: C[M,256] = A[M,256] @ W[256,256] (+epilogue) --------
// MODE 0: bias   b  = x @ g_WU + ub
// MODE 1: iter   G  = y @ g_W ; partial sums of ||y-relu(G+b)||^2 and ||y||^2
template<int MODE>
__launch_bounds__(256, 2)
__global__ void gemm_kernel(const float* __restrict__ Aop,
                            const float* __restrict__ ub) {
    if (MODE == 1 && g_active == 0) return;

    __shared__ float As[16][132];   // [k][m], padded
    __shared__ float Bs[16][128];   // [k][n]

    const float* __restrict__ Ap = (MODE == 0) ? Aop : g_y;
    const float* __restrict__ Bp = (MODE == 0) ? g_WU : g_W;
    float* __restrict__ Cout     = (MODE == 0) ? g_b : g_G;

    const int tid = threadIdx.x;
    const int tx  = tid & 15;      // 0..15  (column pairs)
    const int ty  = tid >> 4;      // 0..15  (row groups of 8)
    const int m0  = blockIdx.y * 128;
    const int n0  = blockIdx.x * 128;

    const int ra = tid >> 2;          // 0..63
    const int ca = (tid & 3) << 2;    // 0,4,8,12
    const int rb = tid >> 5;          // 0..7
    const int cb = (tid & 31) << 2;   // 0..124

    unsigned long long acc[8][4];
#pragma unroll
    for (int i = 0; i < 8; ++i)
#pragma unroll
        for (int j = 0; j < 4; ++j) acc[i][j] = 0ull;

    for (int k0 = 0; k0 < DIM; k0 += 16) {
        float4 a0 = *(const float4*)(Ap + (m0 + ra     ) * DIM + k0 + ca);
        float4 a1 = *(const float4*)(Ap + (m0 + ra + 64) * DIM + k0 + ca);
        float4 b0 = *(const float4*)(Bp + (k0 + rb    ) * DIM + n0 + cb);
        float4 b1 = *(const float4*)(Bp + (k0 + rb + 8) * DIM + n0 + cb);
        __syncthreads();   // previous tile fully consumed
        As[ca+0][ra] = a0.x;  As[ca+1][ra] = a0.y;
        As[ca+2][ra] = a0.z;  As[ca+3][ra] = a0.w;
        As[ca+0][ra+64] = a1.x;  As[ca+1][ra+64] = a1.y;
        As[ca+2][ra+64] = a1.z;  As[ca+3][ra+64] = a1.w;
        *(float4*)&Bs[rb  ][cb] = b0;
        *(float4*)&Bs[rb+8][cb] = b1;
        __syncthreads();
#pragma unroll
        for (int kk = 0; kk < 16; ++kk) {
            unsigned long long pb[4], pa[8];
#pragma unroll
            for (int j = 0; j < 4; ++j)
                pb[j] = *(const unsigned long long*)&Bs[kk][tx*2 + j*32];
#pragma unroll
            for (int i = 0; i < 8; ++i)
                pa[i] = pack2(As[kk][ty*8 + i]);
#pragma unroll
            for (int i = 0; i < 8; ++i)
#pragma unroll
                for (int j = 0; j < 4; ++j)
                    ffma2(acc[i][j], pa[i], pb[j]);
        }
    }

    if (MODE == 0) {
        float2 u[4];
#pragma unroll
        for (int j = 0; j < 4; ++j)
            u[j] = *(const float2*)(ub + n0 + tx*2 + j*32);
#pragma unroll
        for (int i = 0; i < 8; ++i) {
            int m = m0 + ty*8 + i;
            float* base = Cout + m*DIM + n0;
#pragma unroll
            for (int j = 0; j < 4; ++j) {
                float2 g;
                g.x = lo32(acc[i][j]) + u[j].x;
                g.y = hi32(acc[i][j]) + u[j].y;
                *(float2*)(base + tx*2 + j*32) = g;
            }
        }
    } else {
        float sn = 0.f, sd = 0.f;
#pragma unroll
        for (int i = 0; i < 8; ++i) {
            int m = m0 + ty*8 + i;
            const float* brow = g_b + m*DIM + n0;
            const float* yrow = g_y + m*DIM + n0;
            float* base = Cout + m*DIM + n0;
#pragma unroll
            for (int j = 0; j < 4; ++j) {
                int c = tx*2 + j*32;
                float2 bv = *(const float2*)(brow + c);
                float2 yv = *(const float2*)(yrow + c);
                float2 g;
                g.x = lo32(acc[i][j]);
                g.y = hi32(acc[i][j]);
                float fn0 = fmaxf(g.x + bv.x, 0.f);
                float fn1 = fmaxf(g.y + bv.y, 0.f);
                float d0 = yv.x - fn0, d1 = yv.y - fn1;
                sn = fmaf(d0, d0, sn);  sn = fmaf(d1, d1, sn);
                sd = fmaf(yv.x, yv.x, sd);  sd = fmaf(yv.y, yv.y, sd);
                *(float2*)(base + c) = g;
            }
        }
        // deterministic block reduction (no atomics -> bit-stable err)
        __syncthreads();
        float* red = &As[0][0];   // 2112 floats available; need 512
        red[tid]       = sn;
        red[256 + tid] = sd;
        __syncthreads();
#pragma unroll
        for (int s = 128; s > 0; s >>= 1) {
            if (tid < s) {
                red[tid]       += red[tid + s];
                red[256 + tid] += red[256 + tid + s];
            }
            __syncthreads();
        }
        if (tid == 0) {
            int bid = blockIdx.y * NBLK + blockIdx.x;
            g_partial[bid*2    ] = red[0];
            g_partial[bid*2 + 1] = red[256];
        }
    }
}

// ---------------- elementwise FISTA update ----------------
__global__ void update_kernel(float beta) {
    if (g_active == 0) return;
    int i = blockIdx.x * blockDim.x + threadIdx.x;
    float4 y = ((const float4*)g_y)[i];
    float4 G = ((const float4*)g_G)[i];
    float4 b = ((const float4*)g_b)[i];
    float4 x = ((const float4*)g_x)[i];
    float4 xn, yn;
    xn.x = fmaxf(0.5f*(y.x + G.x + b.x), 0.f);
    xn.y = fmaxf(0.5f*(y.y + G.y + b.y), 0.f);
    xn.z = fmaxf(0.5f*(y.z + G.z + b.z), 0.f);
    xn.w = fmaxf(0.5f*(y.w + G.w + b.w), 0.f);
    yn.x = xn.x + beta*(xn.x - x.x);
    yn.y = xn.y + beta*(xn.y - x.y);
    yn.z = xn.z + beta*(xn.z - x.z);
    yn.w = xn.w + beta*(xn.w - x.w);
    ((float4*)g_x)[i] = xn;
    ((float4*)g_y)[i] = yn;
}

// ---------------- convergence check ----------------
__global__ void check_kernel() {
    if (g_active == 0) return;
    __shared__ float sn[256], sd[256];
    int t = threadIdx.x;
    float a = g_partial[2*t      ] + g_partial[2*(t + 256)    ];
    float b = g_partial[2*t + 1  ] + g_partial[2*(t + 256) + 1];
    sn[t] = a; sd[t] = b;
    __syncthreads();
#pragma unroll
    for (int s = 128; s > 0; s >>= 1) {
        if (t < s) { sn[t] += sn[t + s]; sd[t] += sd[t + s]; }
        __syncthreads();
    }
    if (t == 0) {
        float err = sqrtf(sn[0]) / (1e-6f + sqrtf(sd[0]));
        if (!(err > 1e-4f)) g_active = 0;   // loop continues only while err > TOL
    }
}

// ---------------- final layer: out = relu(G + b) ----------------
__global__ void final_kernel(float* __restrict__ out) {
    int i = blockIdx.x * blockDim.x + threadIdx.x;
    float4 G = ((const float4*)g_G)[i];
    float4 b = ((const float4*)g_b)[i];
    float4 o;
    o.x = fmaxf(G.x + b.x, 0.f);
    o.y = fmaxf(G.y + b.y, 0.f);
    o.z = fmaxf(G.z + b.z, 0.f);
    o.w = fmaxf(G.w + b.w, 0.f);
    ((float4*)out)[i] = o;
}

// ---------------- launch ----------------
extern "C" void kernel_launch(void* const* d_in, const int* in_sizes, int n_in,
                              void* d_out, int out_size) {
    const float* x  = (const float*)d_in[0];
    const float* U  = (const float*)d_in[1];
    const float* ub = (const float*)d_in[2];
    const float* A  = (const float*)d_in[3];
    const float* B  = (const float*)d_in[4];
    (void)in_sizes; (void)n_in; (void)out_size;

    prep_kernel<<<DIM, DIM>>>(U, A, B);
    init_kernel<<<EW_GRID, 256>>>();

    dim3 ggrid(NBLK, MBLK);
    gemm_kernel<0><<<ggrid, 256>>>(x, ub);   // b = x @ U^T + ub

    float t = 1.0f;
    for (int it = 0; it < MAX_IT; ++it) {
        float tn   = 0.5f * (1.0f + sqrtf(1.0f + 4.0f * t * t));
        float beta = (t - 1.0f) / tn;
        update_kernel<<<EW_GRID, 256>>>(beta);          // x,y <- prox + momentum
        gemm_kernel<1><<<ggrid, 256>>>(nullptr, nullptr); // G = y @ Weff, err partials
        check_kernel<<<1, 256>>>();                      // err vs TOL -> g_active
        t = tn;
    }

    final_kernel<<<EW_GRID, 256>>>((float*)d_out);       // relu(G + b)
}